// round 12
// baseline (speedup 1.0000x reference)
#include <cuda_runtime.h>

#define BATCH 64
#define KPTS  2048
#define NTHR  128
#define RI    8
#define TI    (NTHR * RI)          // 1024 query (P) points per block
#define NI    (KPTS / TI)          // 2 i-chunks
#define TJ    128                  // target (T) tile per block (halved: more blocks)
#define NJ    (KPTS / TJ)          // 16 j-chunks
#define DUP   64                   // wrap duplication for lane-staggered j
#define NENT  (BATCH * KPTS)       // 131072 entries per side
#define INF_BITS 0x7f800000
#define RBLK  1024
#define RTHR  128

typedef unsigned long long ull;

// partial minima (plain stores -> no init kernel, no global atomics)
__device__ float g_rowp[NJ * NENT];   // [jc][b*KPTS + i]   min over j-chunk (8 MB)
__device__ int   g_colp[NI * NENT];   // [ic][b*KPTS + j]   min over i-chunk (bits)
__device__ float g_part[RBLK];
__device__ unsigned int g_ticket;     // zero-init; last reduce block resets

// ---------- f32x2 packed helpers ----------
__device__ __forceinline__ ull pk(float a, float b) {
    ull r; asm("mov.b64 %0, {%1,%2};" : "=l"(r) : "f"(a), "f"(b)); return r;
}
__device__ __forceinline__ void upk(ull v, float& a, float& b) {
    asm("mov.b64 {%0,%1}, %2;" : "=f"(a), "=f"(b) : "l"(v));
}
__device__ __forceinline__ ull fma2(ull a, ull b, ull c) {
    ull d; asm("fma.rn.f32x2 %0, %1, %2, %3;" : "=l"(d) : "l"(a), "l"(b), "l"(c)); return d;
}
__device__ __forceinline__ ull add2(ull a, ull b) {
    ull d; asm("add.rn.f32x2 %0, %1, %2;" : "=l"(d) : "l"(a), "l"(b)); return d;
}

// ---------- main: 8 i x 1 j per thread-iter; 2048 blocks -> 9 warps/SMSP ----------
__global__ void __launch_bounds__(NTHR, 9)
chamfer_main(const float* __restrict__ P, const float* __restrict__ T) {
    __shared__ ulonglong2 sA[TJ + DUP];   // {(-2tx,-2tx), (-2ty,-2ty)}
    __shared__ ull        sB[TJ + DUP];   // {t2, t2}
    __shared__ int        sCol[TJ + DUP]; // partial colmin bits

    const int b   = blockIdx.z;
    const int ic  = blockIdx.y;
    const int jc  = blockIdx.x;
    const int tid = threadIdx.x;

    const float* Pb = P + b * (2 * KPTS);
    const float* Tb = T + b * (2 * KPTS);
    const int jbase = jc * TJ;

    // stage target tile (with DUP-entry wrap duplication)
    for (int t = tid; t < TJ + DUP; t += NTHR) {
        int j = jbase + (t & (TJ - 1));
        float tx = Tb[j];
        float ty = Tb[KPTS + j];
        float m2x = -2.0f * tx, m2y = -2.0f * ty;
        sA[t] = make_ulonglong2(pk(m2x, m2x), pk(m2y, m2y));
        float t2 = tx * tx + ty * ty;
        sB[t] = pk(t2, t2);
        sCol[t] = INF_BITS;
    }

    // per-thread predicted points (8 consecutive i, two vectorized loads)
    const int i0 = ic * TI + tid * RI;
    float4 xa = *reinterpret_cast<const float4*>(Pb + i0);
    float4 xb = *reinterpret_cast<const float4*>(Pb + i0 + 4);
    float4 ya = *reinterpret_cast<const float4*>(Pb + KPTS + i0);
    float4 yb = *reinterpret_cast<const float4*>(Pb + KPTS + i0 + 4);

    ull px01 = pk(xa.x, xa.y), px23 = pk(xa.z, xa.w);
    ull px45 = pk(xb.x, xb.y), px67 = pk(xb.z, xb.w);
    ull py01 = pk(ya.x, ya.y), py23 = pk(ya.z, ya.w);
    ull py45 = pk(yb.x, yb.y), py67 = pk(yb.z, yb.w);

    float p0 = xa.x * xa.x + ya.x * ya.x;
    float p1 = xa.y * xa.y + ya.y * ya.y;
    float p2 = xa.z * xa.z + ya.z * ya.z;
    float p3 = xa.w * xa.w + ya.w * ya.w;
    float p4 = xb.x * xb.x + yb.x * yb.x;
    float p5 = xb.y * xb.y + yb.y * yb.y;
    float p6 = xb.z * xb.z + yb.z * yb.z;
    float p7 = xb.w * xb.w + yb.w * yb.w;
    ull pp01 = pk(p0, p1), pp23 = pk(p2, p3);
    ull pp45 = pk(p4, p5), pp67 = pk(p6, p7);

    const float FINF = __int_as_float(INF_BITS);
    float r0 = FINF, r1 = FINF, r2 = FINF, r3 = FINF;
    float r4 = FINF, r5 = FINF, r6 = FINF, r7 = FINF;

    // lane-staggered start: intra-warp distinct j (conflict-free LDS + spread ATOMS)
    const int off = (tid & 31) + ((tid >> 5) << 3);   // 0..55 (< DUP)

    __syncthreads();

    // depth-1 software pipeline: prefetch idx+1 while computing idx.
    // max prefetch index = 55 + (TJ-1) + 1 = 183 < TJ+DUP=192 (in-bounds).
    ulonglong2 A = sA[off];
    ull        c2 = sB[off];

#pragma unroll 8
    for (int jt = 0; jt < TJ; ++jt) {
        const int idx  = off + jt;
        ulonglong2 An  = sA[idx + 1];     // prefetch next (LDS in flight)
        ull        c2n = sB[idx + 1];

        ull w0 = fma2(py01, A.y, fma2(px01, A.x, add2(c2, pp01)));
        ull w1 = fma2(py23, A.y, fma2(px23, A.x, add2(c2, pp23)));
        ull w2 = fma2(py45, A.y, fma2(px45, A.x, add2(c2, pp45)));
        ull w3 = fma2(py67, A.y, fma2(px67, A.x, add2(c2, pp67)));

        float a0, b0, a1, b1, a2, b2, a3, b3;
        upk(w0, a0, b0); upk(w1, a1, b1);
        upk(w2, a2, b2); upk(w3, a3, b3);

        r0 = fminf(r0, a0); r1 = fminf(r1, b0);
        r2 = fminf(r2, a1); r3 = fminf(r3, b1);
        r4 = fminf(r4, a2); r5 = fminf(r5, b2);
        r6 = fminf(r6, a3); r7 = fminf(r7, b3);

        float m = fminf(fminf(fminf(a0, b0), fminf(a1, b1)),
                        fminf(fminf(a2, b2), fminf(a3, b3)));
        atomicMin(&sCol[idx], __float_as_int(m));   // spread-address ATOMS

        A = An; c2 = c2n;
    }

    __syncthreads();

    // fold wrap duplicates back (exclusive after barrier)
    if (tid < DUP) {
        int v = sCol[TJ + tid];
        if (v < sCol[tid]) sCol[tid] = v;
    }
    __syncthreads();

    // publish block partials (plain stores into per-chunk slabs)
    for (int t = tid; t < TJ; t += NTHR)
        g_colp[ic * NENT + b * KPTS + jbase + t] = sCol[t];

    float* rp = &g_rowp[jc * NENT + b * KPTS + i0];
    *reinterpret_cast<float4*>(rp)     = make_float4(r0, r1, r2, r3);
    *reinterpret_cast<float4*>(rp + 4) = make_float4(r4, r5, r6, r7);
}

// ---------- fused reduce: 1024 small blocks, ticketed final ----------
__global__ void __launch_bounds__(RTHR)
reduce_all(float* out) {
    __shared__ float ss[RTHR];
    const int tid = threadIdx.x;

    float s;
    if (blockIdx.x < RBLK / 2) {       // row side: blocks [0,512)
        const int base = (blockIdx.x * RTHR + tid) * 2;
        float2 m = *reinterpret_cast<const float2*>(&g_rowp[base]);
#pragma unroll
        for (int c = 1; c < NJ; ++c) {
            float2 v = *reinterpret_cast<const float2*>(&g_rowp[c * NENT + base]);
            m.x = fminf(m.x, v.x); m.y = fminf(m.y, v.y);
        }
        s = sqrtf(fmaxf(m.x, 0.0f)) + sqrtf(fmaxf(m.y, 0.0f));
    } else {                           // col side: blocks [512,1024)
        const int base = ((blockIdx.x - RBLK / 2) * RTHR + tid) * 2;
        int2 m = *reinterpret_cast<const int2*>(&g_colp[base]);
#pragma unroll
        for (int c = 1; c < NI; ++c) {
            int2 v = *reinterpret_cast<const int2*>(&g_colp[c * NENT + base]);
            m.x = min(m.x, v.x); m.y = min(m.y, v.y);
        }
        s = sqrtf(fmaxf(__int_as_float(m.x), 0.0f))
          + sqrtf(fmaxf(__int_as_float(m.y), 0.0f));
    }

    ss[tid] = s;
    __syncthreads();
#pragma unroll
    for (int st = RTHR / 2; st > 0; st >>= 1) {
        if (tid < st) ss[tid] += ss[tid + st];
        __syncthreads();
    }

    __shared__ bool amLast;
    if (tid == 0) {
        g_part[blockIdx.x] = ss[0];
        __threadfence();
        unsigned int t = atomicAdd(&g_ticket, 1u);
        amLast = (t == RBLK - 1);
    }
    __syncthreads();

    if (amLast) {
        __threadfence();
        float acc = 0.0f;
#pragma unroll
        for (int c = 0; c < RBLK / RTHR; ++c)
            acc += g_part[c * RTHR + tid];
        ss[tid] = acc;
        __syncthreads();
#pragma unroll
        for (int st = RTHR / 2; st > 0; st >>= 1) {
            if (tid < st) ss[tid] += ss[tid + st];
            __syncthreads();
        }
        if (tid == 0) {
            out[0] = ss[0] * (1.0f / (float)(BATCH * KPTS));
            g_ticket = 0;               // reset for next graph replay
        }
    }
}

extern "C" void kernel_launch(void* const* d_in, const int* in_sizes, int n_in,
                              void* d_out, int out_size) {
    const float* P = (const float*)d_in[0];   // predicted (64, 4096)
    const float* T = (const float*)d_in[1];   // target    (64, 4096)
    (void)in_sizes; (void)n_in; (void)out_size;

    dim3 grid(NJ, NI, BATCH);                 // 16 x 2 x 64 = 2048 blocks
    chamfer_main<<<grid, NTHR>>>(P, T);
    reduce_all<<<RBLK, RTHR>>>((float*)d_out);
}

// round 13
// speedup vs baseline: 1.1197x; 1.1197x over previous
#include <cuda_runtime.h>

#define BATCH 64
#define KPTS  2048
#define NTHR  128
#define RI    8
#define TI    (NTHR * RI)          // 1024 query (P) points per block
#define NI    (KPTS / TI)          // 2 i-chunks
#define TJ    256                  // target (T) tile per block
#define NJ    (KPTS / TJ)          // 8 j-chunks
#define DUP   64                   // wrap duplication for lane-staggered j
#define NENT  (BATCH * KPTS)       // 131072 entries per side
#define INF_BITS 0x7f800000
#define RBLK  1024
#define RTHR  128

typedef unsigned long long ull;

// partial minima as float-bit s32 (plain stores -> no init, no global atomics)
__device__ int   g_rowp[NJ * NENT];   // [jc][b*KPTS + i]   min over j-chunk (bits)
__device__ int   g_colp[NI * NENT];   // [ic][b*KPTS + j]   min over i-chunk (bits)
__device__ float g_part[RBLK];
__device__ unsigned int g_ticket;     // zero-init; last reduce block resets

// ---------- f32x2 packed helpers ----------
__device__ __forceinline__ ull pk(float a, float b) {
    ull r; asm("mov.b64 %0, {%1,%2};" : "=l"(r) : "f"(a), "f"(b)); return r;
}
__device__ __forceinline__ void upki(ull v, int& a, int& b) {
    float x, y;
    asm("mov.b64 {%0,%1}, %2;" : "=f"(x), "=f"(y) : "l"(v));
    a = __float_as_int(x); b = __float_as_int(y);
}
__device__ __forceinline__ ull fma2(ull a, ull b, ull c) {
    ull d; asm("fma.rn.f32x2 %0, %1, %2, %3;" : "=l"(d) : "l"(a), "l"(b), "l"(c)); return d;
}
__device__ __forceinline__ ull add2(ull a, ull b) {
    ull d; asm("add.rn.f32x2 %0, %1, %2;" : "=l"(d) : "l"(a), "l"(b)); return d;
}
// 3-input s32 min (VIMNMX3 on sm_90+; correct on float bits given final clamp>=0)
__device__ __forceinline__ int min3i(int a, int b, int c) {
    return __vimin3_s32(a, b, c);
}

// ---------- main: 8 i x 2 j per body; all mins as s32-on-bits with min3 ----------
__global__ void __launch_bounds__(NTHR, 6)
chamfer_main(const float* __restrict__ P, const float* __restrict__ T) {
    __shared__ ulonglong2 sA[TJ + DUP];   // {(-2tx,-2tx), (-2ty,-2ty)}
    __shared__ ull        sB[TJ + DUP];   // {t2, t2}
    __shared__ int        sCol[TJ + DUP]; // partial colmin bits

    const int b   = blockIdx.z;
    const int ic  = blockIdx.y;
    const int jc  = blockIdx.x;
    const int tid = threadIdx.x;

    const float* Pb = P + b * (2 * KPTS);
    const float* Tb = T + b * (2 * KPTS);
    const int jbase = jc * TJ;

    // stage target tile (with DUP-entry wrap duplication)
    for (int t = tid; t < TJ + DUP; t += NTHR) {
        int j = jbase + (t & (TJ - 1));
        float tx = Tb[j];
        float ty = Tb[KPTS + j];
        float m2x = -2.0f * tx, m2y = -2.0f * ty;
        sA[t] = make_ulonglong2(pk(m2x, m2x), pk(m2y, m2y));
        float t2 = tx * tx + ty * ty;
        sB[t] = pk(t2, t2);
        sCol[t] = INF_BITS;
    }

    // per-thread predicted points (8 consecutive i, two vectorized loads)
    const int i0 = ic * TI + tid * RI;
    float4 xa = *reinterpret_cast<const float4*>(Pb + i0);
    float4 xb = *reinterpret_cast<const float4*>(Pb + i0 + 4);
    float4 ya = *reinterpret_cast<const float4*>(Pb + KPTS + i0);
    float4 yb = *reinterpret_cast<const float4*>(Pb + KPTS + i0 + 4);

    ull px01 = pk(xa.x, xa.y), px23 = pk(xa.z, xa.w);
    ull px45 = pk(xb.x, xb.y), px67 = pk(xb.z, xb.w);
    ull py01 = pk(ya.x, ya.y), py23 = pk(ya.z, ya.w);
    ull py45 = pk(yb.x, yb.y), py67 = pk(yb.z, yb.w);

    float p0 = xa.x * xa.x + ya.x * ya.x;
    float p1 = xa.y * xa.y + ya.y * ya.y;
    float p2 = xa.z * xa.z + ya.z * ya.z;
    float p3 = xa.w * xa.w + ya.w * ya.w;
    float p4 = xb.x * xb.x + yb.x * yb.x;
    float p5 = xb.y * xb.y + yb.y * yb.y;
    float p6 = xb.z * xb.z + yb.z * yb.z;
    float p7 = xb.w * xb.w + yb.w * yb.w;
    ull pp01 = pk(p0, p1), pp23 = pk(p2, p3);
    ull pp45 = pk(p4, p5), pp67 = pk(p6, p7);

    int R0 = INF_BITS, R1 = INF_BITS, R2 = INF_BITS, R3 = INF_BITS;
    int R4 = INF_BITS, R5 = INF_BITS, R6 = INF_BITS, R7 = INF_BITS;

    // lane-staggered start: intra-warp distinct j (conflict-free LDS + spread ATOMS)
    const int off = (tid & 31) + ((tid >> 5) << 3);   // 0..55 (< DUP)

    __syncthreads();

#pragma unroll 4
    for (int jt = 0; jt < TJ; jt += 2) {
        const int idx = off + jt;                 // idx, idx+1 <= 310 < 320
        ulonglong2 A0 = sA[idx];
        ull        c0 = sB[idx];
        ulonglong2 A1 = sA[idx + 1];
        ull        c1 = sB[idx + 1];

        // j0 distances (8 i's packed in 4 f32x2)
        ull u0 = fma2(py01, A0.y, fma2(px01, A0.x, add2(c0, pp01)));
        ull u1 = fma2(py23, A0.y, fma2(px23, A0.x, add2(c0, pp23)));
        ull u2 = fma2(py45, A0.y, fma2(px45, A0.x, add2(c0, pp45)));
        ull u3 = fma2(py67, A0.y, fma2(px67, A0.x, add2(c0, pp67)));
        // j1 distances
        ull v0 = fma2(py01, A1.y, fma2(px01, A1.x, add2(c1, pp01)));
        ull v1 = fma2(py23, A1.y, fma2(px23, A1.x, add2(c1, pp23)));
        ull v2 = fma2(py45, A1.y, fma2(px45, A1.x, add2(c1, pp45)));
        ull v3 = fma2(py67, A1.y, fma2(px67, A1.x, add2(c1, pp67)));

        int q0, q1, q2, q3, q4, q5, q6, q7;
        int s0, s1, s2, s3, s4, s5, s6, s7;
        upki(u0, q0, q1); upki(u1, q2, q3); upki(u2, q4, q5); upki(u3, q6, q7);
        upki(v0, s0, s1); upki(v1, s2, s3); upki(v2, s4, s5); upki(v3, s6, s7);

        // col trees (4 min-class ops each)
        int xa0 = min3i(q0, q1, q2);
        int xb0 = min3i(q3, q4, q5);
        int xc0 = min3i(q6, q7, xa0);
        int m0  = min(xb0, xc0);

        int ya1 = min3i(s0, s1, s2);
        int yb1 = min3i(s3, s4, s5);
        int yc1 = min3i(s6, s7, ya1);
        int m1  = min(yb1, yc1);

        atomicMin(&sCol[idx],     m0);    // spread-address ATOMS
        atomicMin(&sCol[idx + 1], m1);

        // row accumulators: fold both j's at once (8 min3)
        R0 = min3i(R0, q0, s0); R1 = min3i(R1, q1, s1);
        R2 = min3i(R2, q2, s2); R3 = min3i(R3, q3, s3);
        R4 = min3i(R4, q4, s4); R5 = min3i(R5, q5, s5);
        R6 = min3i(R6, q6, s6); R7 = min3i(R7, q7, s7);
    }

    __syncthreads();

    // fold wrap duplicates back (exclusive after barrier)
    if (tid < DUP) {
        int v = sCol[TJ + tid];
        if (v < sCol[tid]) sCol[tid] = v;
    }
    __syncthreads();

    // publish block partials (plain stores into per-chunk slabs)
    for (int t = tid; t < TJ; t += NTHR)
        g_colp[ic * NENT + b * KPTS + jbase + t] = sCol[t];

    int* rp = &g_rowp[jc * NENT + b * KPTS + i0];
    *reinterpret_cast<int4*>(rp)     = make_int4(R0, R1, R2, R3);
    *reinterpret_cast<int4*>(rp + 4) = make_int4(R4, R5, R6, R7);
}

// ---------- fused reduce: min over chunks, clamp, sqrt, sum; ticketed final ----------
__global__ void __launch_bounds__(RTHR)
reduce_all(float* out) {
    __shared__ float ss[RTHR];
    const int tid = threadIdx.x;

    float s;
    if (blockIdx.x < RBLK / 2) {       // row side: blocks [0,512)
        const int base = (blockIdx.x * RTHR + tid) * 2;
        int2 m = *reinterpret_cast<const int2*>(&g_rowp[base]);
#pragma unroll
        for (int c = 1; c < NJ; ++c) {
            int2 v = *reinterpret_cast<const int2*>(&g_rowp[c * NENT + base]);
            m.x = min(m.x, v.x); m.y = min(m.y, v.y);
        }
        s = sqrtf(fmaxf(__int_as_float(m.x), 0.0f))
          + sqrtf(fmaxf(__int_as_float(m.y), 0.0f));
    } else {                           // col side: blocks [512,1024)
        const int base = ((blockIdx.x - RBLK / 2) * RTHR + tid) * 2;
        int2 m = *reinterpret_cast<const int2*>(&g_colp[base]);
#pragma unroll
        for (int c = 1; c < NI; ++c) {
            int2 v = *reinterpret_cast<const int2*>(&g_colp[c * NENT + base]);
            m.x = min(m.x, v.x); m.y = min(m.y, v.y);
        }
        s = sqrtf(fmaxf(__int_as_float(m.x), 0.0f))
          + sqrtf(fmaxf(__int_as_float(m.y), 0.0f));
    }

    ss[tid] = s;
    __syncthreads();
#pragma unroll
    for (int st = RTHR / 2; st > 0; st >>= 1) {
        if (tid < st) ss[tid] += ss[tid + st];
        __syncthreads();
    }

    __shared__ bool amLast;
    if (tid == 0) {
        g_part[blockIdx.x] = ss[0];
        __threadfence();
        unsigned int t = atomicAdd(&g_ticket, 1u);
        amLast = (t == RBLK - 1);
    }
    __syncthreads();

    if (amLast) {
        __threadfence();
        float acc = 0.0f;
#pragma unroll
        for (int c = 0; c < RBLK / RTHR; ++c)
            acc += g_part[c * RTHR + tid];
        ss[tid] = acc;
        __syncthreads();
#pragma unroll
        for (int st = RTHR / 2; st > 0; st >>= 1) {
            if (tid < st) ss[tid] += ss[tid + st];
            __syncthreads();
        }
        if (tid == 0) {
            out[0] = ss[0] * (1.0f / (float)(BATCH * KPTS));
            g_ticket = 0;               // reset for next graph replay
        }
    }
}

extern "C" void kernel_launch(void* const* d_in, const int* in_sizes, int n_in,
                              void* d_out, int out_size) {
    const float* P = (const float*)d_in[0];   // predicted (64, 4096)
    const float* T = (const float*)d_in[1];   // target    (64, 4096)
    (void)in_sizes; (void)n_in; (void)out_size;

    dim3 grid(NJ, NI, BATCH);                 // 8 x 2 x 64 = 1024 blocks
    chamfer_main<<<grid, NTHR>>>(P, T);
    reduce_all<<<RBLK, RTHR>>>((float*)d_out);
}